// round 3
// baseline (speedup 1.0000x reference)
#include <cuda_runtime.h>
#include <cuda_bf16.h>
#include <cstdint>

// ---------------- problem constants ----------------
#define NB 96       // nodes / mamba batch
#define TT 160      // sequence length
#define DF 96       // feature dim D
#define EMB 24
#define H2 48       // 2*EMB
#define DINNER 192
#define NGROUPS 6
#define DSTATE 64
#define NH 6        // heads
#define HD 32       // headdim
#define DIN 1158    // D_IN_PROJ (logical)
#define DINP 1160   // padded row stride for g_zx (16B-aligned rows)
#define CONVD 960   // CONV_DIM
#define MROWS (NB*TT)   // 15360

// ---------------- scratch (static device allocations) ----------------
__device__ float g_z[(size_t)MROWS * DF];        // (b,l,c)  5.9MB
__device__ float g_zx[(size_t)MROWS * DINP];     // zxbcdt (padded stride) 71MB
__device__ float g_xc[(size_t)MROWS * CONVD];    // conv+silu out 59MB
__device__ float g_y[(size_t)MROWS * DINNER];    // scan output   11.8MB
__device__ float g_sp[(size_t)NB * 8 * DINNER];  // partial sums for gated mean

__device__ __forceinline__ float softplusf(float x) {
    return fmaxf(x, 0.f) + log1pf(expf(-fabsf(x)));
}
__device__ __forceinline__ float siluf(float x) {
    return x / (1.f + expf(-x));
}
__device__ __forceinline__ float eluf(float x) {
    return x > 0.f ? x : expm1f(x);
}

// =====================================================================
// K1: per-timestep block. embed-aggregate + 2x GEMM(96x96x96) + residual
//     + node-BatchNorm, writes z in (b, l, c) layout.
// =====================================================================
#define K1_SMEM_FLOATS (9216*4 + 4608 + 48 + 192)

__global__ void k1_embed_gnn(const float* __restrict__ input,
                             const int* __restrict__ hem,
                             const int* __restrict__ subnet,
                             const float* __restrict__ gw1,
                             const float* __restrict__ gb1,
                             const float* __restrict__ gw2,
                             const float* __restrict__ gb2,
                             const float* __restrict__ bnw,
                             const float* __restrict__ bnb,
                             const float* __restrict__ hem_emb,
                             const float* __restrict__ sub_emb) {
    extern __shared__ float sm[];
    float* XS  = sm;             // xs[t]   96x96
    float* GIN = XS + 9216;      // gin, later reused as h
    float* H1  = GIN + 9216;     // relu(gin@W1+b1)
    float* WS  = H1 + 9216;      // staged weights
    float* ASM = WS + 9216;      // a[j][c] 96x48
    float* S1  = ASM + 4608;     // s1[c]
    float* RED = S1 + 48;        // mean[96], scale[96]

    const int t = blockIdx.x;
    const int tid = threadIdx.x;

    // load xs[t] : xs[i][c] = input[i, t, c]
    for (int idx = tid; idx < 9216; idx += 256) {
        int i = idx / 96, c = idx % 96;
        XS[idx] = input[(size_t)i * (TT * DF) + t * DF + c];
    }
    // a[j][c]
    for (int idx = tid; idx < 4608; idx += 256) {
        int j = idx / H2, c = idx % H2;
        ASM[idx] = (c < EMB) ? hem_emb[hem[j] * EMB + c]
                             : sub_emb[subnet[j] * EMB + (c - EMB)];
    }
    __syncthreads();

    // s1[c] = sum_i relu(xs[i][c] + a[i][c]) for c < 48
    if (tid < H2) {
        float s = 0.f;
        for (int i = 0; i < NB; i++)
            s += fmaxf(XS[i * 96 + tid] + ASM[i * H2 + tid], 0.f);
        S1[tid] = s;
    }
    __syncthreads();

    // gin[j][c] = xs + (s1 | s2)
    for (int idx = tid; idx < 9216; idx += 256) {
        int j = idx / 96, c = idx % 96;
        float g;
        if (c < H2) {
            g = XS[idx] + S1[c];
        } else {
            float a = ASM[j * H2 + (c - H2)];
            float s = 0.f;
            #pragma unroll 4
            for (int i = 0; i < NB; i++)
                s += fmaxf(XS[i * 96 + c] + a, 0.f);
            g = XS[idx] + s;
        }
        GIN[idx] = g;
    }
    __syncthreads();

    // stage W1
    for (int idx = tid; idx < 9216; idx += 256) WS[idx] = gw1[idx];
    __syncthreads();

    const int tx = tid & 31;   // c base
    const int ty = tid >> 5;   // j base (== warp id)

    // GEMM1: H1 = relu(GIN @ W1 + b1)
    {
        float acc[12][3];
        #pragma unroll
        for (int r = 0; r < 12; r++) { acc[r][0] = 0.f; acc[r][1] = 0.f; acc[r][2] = 0.f; }
        for (int k = 0; k < 96; k++) {
            float w0 = WS[k * 96 + tx];
            float w1 = WS[k * 96 + tx + 32];
            float w2 = WS[k * 96 + tx + 64];
            #pragma unroll
            for (int r = 0; r < 12; r++) {
                float g = GIN[(ty + (r << 3)) * 96 + k];
                acc[r][0] = fmaf(g, w0, acc[r][0]);
                acc[r][1] = fmaf(g, w1, acc[r][1]);
                acc[r][2] = fmaf(g, w2, acc[r][2]);
            }
        }
        float b0 = gb1[tx], b1 = gb1[tx + 32], b2 = gb1[tx + 64];
        #pragma unroll
        for (int r = 0; r < 12; r++) {
            int j = ty + (r << 3);
            H1[j * 96 + tx]      = fmaxf(acc[r][0] + b0, 0.f);
            H1[j * 96 + tx + 32] = fmaxf(acc[r][1] + b1, 0.f);
            H1[j * 96 + tx + 64] = fmaxf(acc[r][2] + b2, 0.f);
        }
    }
    __syncthreads();

    // stage W2
    for (int idx = tid; idx < 9216; idx += 256) WS[idx] = gw2[idx];
    __syncthreads();

    // GEMM2: h = H1 @ W2 + b2 + xs   (write into GIN, reused as h)
    {
        float acc[12][3];
        #pragma unroll
        for (int r = 0; r < 12; r++) { acc[r][0] = 0.f; acc[r][1] = 0.f; acc[r][2] = 0.f; }
        for (int k = 0; k < 96; k++) {
            float w0 = WS[k * 96 + tx];
            float w1 = WS[k * 96 + tx + 32];
            float w2 = WS[k * 96 + tx + 64];
            #pragma unroll
            for (int r = 0; r < 12; r++) {
                float g = H1[(ty + (r << 3)) * 96 + k];
                acc[r][0] = fmaf(g, w0, acc[r][0]);
                acc[r][1] = fmaf(g, w1, acc[r][1]);
                acc[r][2] = fmaf(g, w2, acc[r][2]);
            }
        }
        float b0 = gb2[tx], b1 = gb2[tx + 32], b2 = gb2[tx + 64];
        #pragma unroll
        for (int r = 0; r < 12; r++) {
            int j = ty + (r << 3);
            GIN[j * 96 + tx]      = acc[r][0] + b0 + XS[j * 96 + tx];
            GIN[j * 96 + tx + 32] = acc[r][1] + b1 + XS[j * 96 + tx + 32];
            GIN[j * 96 + tx + 64] = acc[r][2] + b2 + XS[j * 96 + tx + 64];
        }
    }
    __syncthreads();

    // node-wise BatchNorm: stats over j per feature c
    if (tid < 96) {
        const int c = tid;
        float m = 0.f;
        for (int j = 0; j < 96; j++) m += GIN[j * 96 + c];
        m *= (1.f / 96.f);
        float v = 0.f;
        for (int j = 0; j < 96; j++) { float d = GIN[j * 96 + c] - m; v = fmaf(d, d, v); }
        v *= (1.f / 96.f);
        RED[c] = m;
        RED[96 + c] = rsqrtf(v + 1e-5f) * bnw[c];
    }
    __syncthreads();

    // write z[b=j, l=t, c]
    for (int idx = tid; idx < 9216; idx += 256) {
        int j = idx / 96, c = idx % 96;
        float out = (GIN[idx] - RED[c]) * RED[96 + c] + bnb[c];
        g_z[(size_t)j * (TT * DF) + t * DF + c] = out;
    }
}

// =====================================================================
// K2: zxbcdt = z (15360x96) @ in_proj (96x1158)
// 128x128 tile, 8x8 microtile, full K=96 staged in smem.
// Output rows use padded stride DINP.
// =====================================================================
#define K2_SMEM_FLOATS (96*132 + 96*128)

__global__ void __launch_bounds__(256, 2) k2_inproj(const float* __restrict__ W) {
    extern __shared__ float sm[];
    float* As = sm;              // As[k*132 + m]
    float* Bs = As + 96 * 132;   // Bs[k*128 + n]

    const int m0 = blockIdx.x * 128;
    const int n0 = blockIdx.y * 128;
    const int tid = threadIdx.x;

    // A tile: 128 rows x 96 k, transposed into As[k][m]; float4 over k
    for (int idx = tid; idx < 128 * 24; idx += 256) {
        int m = idx / 24, k4 = idx % 24;
        float4 v = *reinterpret_cast<const float4*>(&g_z[(size_t)(m0 + m) * 96 + k4 * 4]);
        As[(k4 * 4 + 0) * 132 + m] = v.x;
        As[(k4 * 4 + 1) * 132 + m] = v.y;
        As[(k4 * 4 + 2) * 132 + m] = v.z;
        As[(k4 * 4 + 3) * 132 + m] = v.w;
    }
    for (int idx = tid; idx < 96 * 128; idx += 256) {
        int k = idx / 128, n = idx % 128;
        int gn = n0 + n;
        Bs[k * 128 + n] = (gn < DIN) ? W[(size_t)k * DIN + gn] : 0.f;
    }
    __syncthreads();

    const int tx = tid & 15;    // n
    const int ty = tid >> 4;    // m
    const int mt = ty * 8, nt = tx * 8;

    float acc[8][8];
    #pragma unroll
    for (int i = 0; i < 8; i++)
        #pragma unroll
        for (int j = 0; j < 8; j++) acc[i][j] = 0.f;

    #pragma unroll 4
    for (int k = 0; k < 96; k++) {
        float4 a0 = *reinterpret_cast<const float4*>(&As[k * 132 + mt]);
        float4 a1 = *reinterpret_cast<const float4*>(&As[k * 132 + mt + 4]);
        float4 b0 = *reinterpret_cast<const float4*>(&Bs[k * 128 + nt]);
        float4 b1 = *reinterpret_cast<const float4*>(&Bs[k * 128 + nt + 4]);
        float av[8] = {a0.x, a0.y, a0.z, a0.w, a1.x, a1.y, a1.z, a1.w};
        float bv[8] = {b0.x, b0.y, b0.z, b0.w, b1.x, b1.y, b1.z, b1.w};
        #pragma unroll
        for (int i = 0; i < 8; i++)
            #pragma unroll
            for (int j = 0; j < 8; j++)
                acc[i][j] = fmaf(av[i], bv[j], acc[i][j]);
    }

    #pragma unroll
    for (int i = 0; i < 8; i++) {
        size_t mrow = (size_t)(m0 + mt + i) * DINP;
        #pragma unroll
        for (int j = 0; j < 8; j++) {
            int n = n0 + nt + j;
            if (n < DIN) g_zx[mrow + n] = acc[i][j];
        }
    }
}

// =====================================================================
// K3: depthwise causal conv(4) + SiLU on xBC = zx[:, 192:1152]
// float4 vectorized over channels (CONVD = 960 = 240 float4)
// g_zx rows are DINP-strided (16B aligned), so float4 loads are legal.
// =====================================================================
__global__ void k3_conv(const float* __restrict__ conv_w,
                        const float* __restrict__ conv_b) {
    int idx = blockIdx.x * 256 + threadIdx.x;     // over MROWS * 240
    if (idx >= MROWS * (CONVD / 4)) return;
    int c4 = idx % (CONVD / 4);
    int bl = idx / (CONVD / 4);
    int l  = bl % TT;
    int b  = bl / TT;
    const int c = c4 * 4;

    float4 acc = *reinterpret_cast<const float4*>(conv_b + c);
    // weights for 4 consecutive channels: w[c+j][k]
    float4 w0 = *reinterpret_cast<const float4*>(conv_w + (c + 0) * 4);
    float4 w1 = *reinterpret_cast<const float4*>(conv_w + (c + 1) * 4);
    float4 w2 = *reinterpret_cast<const float4*>(conv_w + (c + 2) * 4);
    float4 w3 = *reinterpret_cast<const float4*>(conv_w + (c + 3) * 4);
    const float wk[4][4] = {{w0.x, w1.x, w2.x, w3.x},
                            {w0.y, w1.y, w2.y, w3.y},
                            {w0.z, w1.z, w2.z, w3.z},
                            {w0.w, w1.w, w2.w, w3.w}};
    #pragma unroll
    for (int k = 0; k < 4; k++) {
        int li = l + k - 3;
        if (li >= 0) {
            float4 v = *reinterpret_cast<const float4*>(
                &g_zx[(size_t)(b * TT + li) * DINP + DINNER + c]);
            acc.x = fmaf(v.x, wk[k][0], acc.x);
            acc.y = fmaf(v.y, wk[k][1], acc.y);
            acc.z = fmaf(v.z, wk[k][2], acc.z);
            acc.w = fmaf(v.w, wk[k][3], acc.w);
        }
    }
    float4 o;
    o.x = siluf(acc.x); o.y = siluf(acc.y); o.z = siluf(acc.z); o.w = siluf(acc.w);
    *reinterpret_cast<float4*>(&g_xc[(size_t)bl * CONVD + c]) = o;
}

// =====================================================================
// K4: selective scan. block = (b, h); 256 threads hold state[32][64]
// thread t: p = t/8 (row), owns n in [ (t&7)*8, +8 ).
// 1-step software prefetch to hide L2 latency.
// =====================================================================
__global__ void __launch_bounds__(256, 4) k4_scan(const float* __restrict__ A_log,
                        const float* __restrict__ Dpar,
                        const float* __restrict__ dt_bias) {
    const int b = blockIdx.x;
    const int h = blockIdx.y;
    const int tid = threadIdx.x;
    const int p = tid >> 3;
    const int kk = tid & 7;

    const float A   = -expf(A_log[h]);
    const float Dp  = Dpar[h];
    const float dtb = dt_bias[h];

    const float* xc  = g_xc + (size_t)b * TT * CONVD;
    const float* dtp = g_zx + (size_t)b * TT * DINP + (DIN - NH) + h;
    float* yout = g_y + (size_t)b * TT * DINNER + h * HD + p;

    const int xoff = h * HD + p;
    const int boff = DINNER + h * DSTATE + kk * 8;
    const int coff = DINNER + NGROUPS * DSTATE + h * DSTATE + kk * 8;

    float st[8];
    #pragma unroll
    for (int i = 0; i < 8; i++) st[i] = 0.f;

    // prefetch l = 0
    float  x   = xc[xoff];
    float4 B0  = *reinterpret_cast<const float4*>(xc + boff);
    float4 B1  = *reinterpret_cast<const float4*>(xc + boff + 4);
    float4 C0  = *reinterpret_cast<const float4*>(xc + coff);
    float4 C1  = *reinterpret_cast<const float4*>(xc + coff + 4);
    float  dtr = dtp[0];

    for (int l = 0; l < TT; l++) {
        float xn = 0.f, dtrn = 0.f;
        float4 B0n = {}, B1n = {}, C0n = {}, C1n = {};
        if (l < TT - 1) {
            const float* row = xc + (size_t)(l + 1) * CONVD;
            xn   = row[xoff];
            B0n  = *reinterpret_cast<const float4*>(row + boff);
            B1n  = *reinterpret_cast<const float4*>(row + boff + 4);
            C0n  = *reinterpret_cast<const float4*>(row + coff);
            C1n  = *reinterpret_cast<const float4*>(row + coff + 4);
            dtrn = dtp[(size_t)(l + 1) * DINP];
        }

        float dt = softplusf(dtr + dtb);
        float dA = expf(dt * A);
        float cf = dt * x;

        st[0] = fmaf(st[0], dA, cf * B0.x);
        st[1] = fmaf(st[1], dA, cf * B0.y);
        st[2] = fmaf(st[2], dA, cf * B0.z);
        st[3] = fmaf(st[3], dA, cf * B0.w);
        st[4] = fmaf(st[4], dA, cf * B1.x);
        st[5] = fmaf(st[5], dA, cf * B1.y);
        st[6] = fmaf(st[6], dA, cf * B1.z);
        st[7] = fmaf(st[7], dA, cf * B1.w);

        float yp = st[0] * C0.x + st[1] * C0.y + st[2] * C0.z + st[3] * C0.w
                 + st[4] * C1.x + st[5] * C1.y + st[6] * C1.z + st[7] * C1.w;
        yp += __shfl_down_sync(0xffffffffu, yp, 4);
        yp += __shfl_down_sync(0xffffffffu, yp, 2);
        yp += __shfl_down_sync(0xffffffffu, yp, 1);
        if (kk == 0) yout[(size_t)l * DINNER] = fmaf(Dp, x, yp);

        x = xn; B0 = B0n; B1 = B1n; C0 = C0n; C1 = C1n; dtr = dtrn;
    }
}

// =====================================================================
// K5: yg = y * silu(zg); RMSNorm over 192; partial sum over L chunk.
// grid (96, 8), 192 threads. writes g_sp[b][chunk][c].
// =====================================================================
__global__ void k5_gate(const float* __restrict__ norm_w) {
    const int b = blockIdx.x;
    const int ch = blockIdx.y;
    const int c = threadIdx.x;  // 0..191
    const int warp = c >> 5, lane = c & 31;

    __shared__ float red[6];
    __shared__ float ssb;

    const float nw = norm_w[c];
    float acc = 0.f;

    for (int l = ch * 20; l < ch * 20 + 20; l++) {
        size_t r = (size_t)(b * TT + l);
        float y  = g_y[r * DINNER + c];
        float zv = g_zx[r * DINP + c];
        float yg = y * siluf(zv);
        float s = yg * yg;
        #pragma unroll
        for (int o = 16; o > 0; o >>= 1) s += __shfl_down_sync(0xffffffffu, s, o);
        if (lane == 0) red[warp] = s;
        __syncthreads();
        if (c == 0) {
            float tot = red[0] + red[1] + red[2] + red[3] + red[4] + red[5];
            ssb = rsqrtf(tot * (1.f / 192.f) + 1e-5f);
        }
        __syncthreads();
        acc = fmaf(yg * ssb, nw, acc);
    }
    g_sp[((size_t)b * 8 + ch) * DINNER + c] = acc;
}

// =====================================================================
// K6: e = (sum over L)/160 @ out_proj, then head. grid 96 blocks x 96 thr.
// out layout: x1[96*96] | mu[96*64] | sigma[96*64]
// =====================================================================
__global__ void k6_head(const float* __restrict__ out_proj,
                        const float* __restrict__ ofw,
                        const float* __restrict__ ofb,
                        const float* __restrict__ mu_w,
                        const float* __restrict__ mu_b,
                        const float* __restrict__ sg_w,
                        const float* __restrict__ sg_b,
                        float* __restrict__ out) {
    const int b = blockIdx.x;
    const int tid = threadIdx.x;  // 0..95
    __shared__ float sb[192], es[96], x1s[96];

    for (int idx = tid; idx < 192; idx += 96) {
        float s = 0.f;
        #pragma unroll
        for (int chk = 0; chk < 8; chk++)
            s += g_sp[((size_t)b * 8 + chk) * DINNER + idx];
        sb[idx] = s * (1.f / 160.f);
    }
    __syncthreads();

    {
        float e = 0.f;
        for (int k = 0; k < 192; k++) e = fmaf(sb[k], out_proj[k * 96 + tid], e);
        es[tid] = e;
    }
    __syncthreads();

    {
        float v = ofb[tid];
        for (int k = 0; k < 96; k++) v = fmaf(es[k], ofw[k * 96 + tid], v);
        v = tanhf(v);
        v = eluf(v);
        x1s[tid] = v;
        out[(size_t)b * 96 + tid] = v;
    }
    __syncthreads();

    if (tid < 64) {
        float m = mu_b[tid], sg = sg_b[tid];
        for (int k = 0; k < 96; k++) {
            m  = fmaf(x1s[k], mu_w[k * 64 + tid], m);
            sg = fmaf(x1s[k], sg_w[k * 64 + tid], sg);
        }
        out[96 * 96 + (size_t)b * 64 + tid] = m;
        out[96 * 96 + 96 * 64 + (size_t)b * 64 + tid] = eluf(sg) + 1.f + 1e-14f;
    }
}

// =====================================================================
extern "C" void kernel_launch(void* const* d_in, const int* in_sizes, int n_in,
                              void* d_out, int out_size) {
    const float* input   = (const float*)d_in[0];
    const int*   hem     = (const int*)  d_in[1];
    const int*   subnet  = (const int*)  d_in[2];
    const float* gine_w1 = (const float*)d_in[3];
    const float* gine_b1 = (const float*)d_in[4];
    const float* gine_w2 = (const float*)d_in[5];
    const float* gine_b2 = (const float*)d_in[6];
    const float* bn_w    = (const float*)d_in[7];
    const float* bn_b    = (const float*)d_in[8];
    const float* hem_emb = (const float*)d_in[9];
    const float* sub_emb = (const float*)d_in[10];
    const float* in_proj = (const float*)d_in[11];
    const float* conv_w  = (const float*)d_in[12];
    const float* conv_b  = (const float*)d_in[13];
    const float* dt_bias = (const float*)d_in[14];
    const float* A_log   = (const float*)d_in[15];
    const float* Dparam  = (const float*)d_in[16];
    const float* norm_w  = (const float*)d_in[17];
    const float* out_proj= (const float*)d_in[18];
    const float* out_fc_w= (const float*)d_in[19];
    const float* out_fc_b= (const float*)d_in[20];
    const float* mu_w    = (const float*)d_in[21];
    const float* mu_b    = (const float*)d_in[22];
    const float* sigma_w = (const float*)d_in[23];
    const float* sigma_b = (const float*)d_in[24];

    const int smem1 = K1_SMEM_FLOATS * 4;
    const int smem2 = K2_SMEM_FLOATS * 4;
    cudaFuncSetAttribute(k1_embed_gnn, cudaFuncAttributeMaxDynamicSharedMemorySize, smem1);
    cudaFuncSetAttribute(k2_inproj,    cudaFuncAttributeMaxDynamicSharedMemorySize, smem2);

    k1_embed_gnn<<<TT, 256, smem1>>>(input, hem, subnet, gine_w1, gine_b1,
                                     gine_w2, gine_b2, bn_w, bn_b, hem_emb, sub_emb);
    k2_inproj<<<dim3(MROWS / 128, (DIN + 127) / 128), 256, smem2>>>(in_proj);
    k3_conv<<<(MROWS * (CONVD / 4) + 255) / 256, 256>>>(conv_w, conv_b);
    k4_scan<<<dim3(NB, NH), 256>>>(A_log, Dparam, dt_bias);
    k5_gate<<<dim3(NB, 8), 192>>>(norm_w);
    k6_head<<<NB, 96>>>(out_proj, out_fc_w, out_fc_b, mu_w, mu_b,
                        sigma_w, sigma_b, (float*)d_out);
}

// round 5
// speedup vs baseline: 1.0277x; 1.0277x over previous
#include <cuda_runtime.h>
#include <cuda_bf16.h>
#include <cstdint>

// ---------------- problem constants ----------------
#define NB 96       // nodes / mamba batch
#define TT 160      // sequence length
#define DF 96       // feature dim D
#define EMB 24
#define H2 48       // 2*EMB
#define DINNER 192
#define NGROUPS 6
#define DSTATE 64
#define NH 6        // heads
#define HD 32       // headdim
#define DIN 1158    // D_IN_PROJ (logical)
#define DINP 1160   // padded row stride for g_zx (16B-aligned rows)
#define CONVD 960   // CONV_DIM
#define MROWS (NB*TT)   // 15360
#define CHUNK 16    // k4 smem staging depth

// ---------------- scratch (static device allocations) ----------------
__device__ float g_z[(size_t)MROWS * DF];
__device__ float g_zx[(size_t)MROWS * DINP];
__device__ float g_xc[(size_t)MROWS * CONVD];
__device__ float g_y[(size_t)MROWS * DINNER];
__device__ float g_sp[(size_t)NB * 8 * DINNER];
__device__ float g_dt[(size_t)NB * NH * TT];
__device__ float g_dA[(size_t)NB * NH * TT];

__device__ __forceinline__ float softplusf(float x) {
    return fmaxf(x, 0.f) + log1pf(expf(-fabsf(x)));
}
__device__ __forceinline__ float siluf(float x) {
    return x / (1.f + expf(-x));
}
__device__ __forceinline__ float eluf(float x) {
    return x > 0.f ? x : expm1f(x);
}

// packed fp32x2 helpers (Blackwell FFMA2 — only reachable via PTX)
__device__ __forceinline__ unsigned long long pack2(float lo, float hi) {
    unsigned long long r;
    asm("mov.b64 %0, {%1, %2};" : "=l"(r) : "f"(lo), "f"(hi));
    return r;
}
__device__ __forceinline__ void ffma2(unsigned long long& acc,
                                      unsigned long long a,
                                      unsigned long long b) {
    asm("fma.rn.f32x2 %0, %1, %2, %0;" : "+l"(acc) : "l"(a), "l"(b));
}
__device__ __forceinline__ void unpack2(unsigned long long v, float& lo, float& hi) {
    asm("mov.b64 {%0, %1}, %2;" : "=f"(lo), "=f"(hi) : "l"(v));
}

// =====================================================================
// K1: per-timestep block. embed-aggregate + 2x GEMM(96x96x96) + residual
//     + node-BatchNorm, writes z in (b, l, c) layout.
// =====================================================================
#define K1_SMEM_FLOATS (9216*4 + 4608 + 48 + 192)

__global__ void k1_embed_gnn(const float* __restrict__ input,
                             const int* __restrict__ hem,
                             const int* __restrict__ subnet,
                             const float* __restrict__ gw1,
                             const float* __restrict__ gb1,
                             const float* __restrict__ gw2,
                             const float* __restrict__ gb2,
                             const float* __restrict__ bnw,
                             const float* __restrict__ bnb,
                             const float* __restrict__ hem_emb,
                             const float* __restrict__ sub_emb) {
    extern __shared__ float sm[];
    float* XS  = sm;
    float* GIN = XS + 9216;
    float* H1  = GIN + 9216;
    float* WS  = H1 + 9216;
    float* ASM = WS + 9216;
    float* S1  = ASM + 4608;
    float* RED = S1 + 48;

    const int t = blockIdx.x;
    const int tid = threadIdx.x;

    for (int idx = tid; idx < 9216; idx += 256) {
        int i = idx / 96, c = idx % 96;
        XS[idx] = input[(size_t)i * (TT * DF) + t * DF + c];
    }
    for (int idx = tid; idx < 4608; idx += 256) {
        int j = idx / H2, c = idx % H2;
        ASM[idx] = (c < EMB) ? hem_emb[hem[j] * EMB + c]
                             : sub_emb[subnet[j] * EMB + (c - EMB)];
    }
    __syncthreads();

    if (tid < H2) {
        float s = 0.f;
        for (int i = 0; i < NB; i++)
            s += fmaxf(XS[i * 96 + tid] + ASM[i * H2 + tid], 0.f);
        S1[tid] = s;
    }
    __syncthreads();

    for (int idx = tid; idx < 9216; idx += 256) {
        int j = idx / 96, c = idx % 96;
        float g;
        if (c < H2) {
            g = XS[idx] + S1[c];
        } else {
            float a = ASM[j * H2 + (c - H2)];
            float s = 0.f;
            #pragma unroll 4
            for (int i = 0; i < NB; i++)
                s += fmaxf(XS[i * 96 + c] + a, 0.f);
            g = XS[idx] + s;
        }
        GIN[idx] = g;
    }
    __syncthreads();

    for (int idx = tid; idx < 9216; idx += 256) WS[idx] = gw1[idx];
    __syncthreads();

    const int tx = tid & 31;
    const int ty = tid >> 5;

    {
        float acc[12][3];
        #pragma unroll
        for (int r = 0; r < 12; r++) { acc[r][0] = 0.f; acc[r][1] = 0.f; acc[r][2] = 0.f; }
        for (int k = 0; k < 96; k++) {
            float w0 = WS[k * 96 + tx];
            float w1 = WS[k * 96 + tx + 32];
            float w2 = WS[k * 96 + tx + 64];
            #pragma unroll
            for (int r = 0; r < 12; r++) {
                float g = GIN[(ty + (r << 3)) * 96 + k];
                acc[r][0] = fmaf(g, w0, acc[r][0]);
                acc[r][1] = fmaf(g, w1, acc[r][1]);
                acc[r][2] = fmaf(g, w2, acc[r][2]);
            }
        }
        float b0 = gb1[tx], b1 = gb1[tx + 32], b2 = gb1[tx + 64];
        #pragma unroll
        for (int r = 0; r < 12; r++) {
            int j = ty + (r << 3);
            H1[j * 96 + tx]      = fmaxf(acc[r][0] + b0, 0.f);
            H1[j * 96 + tx + 32] = fmaxf(acc[r][1] + b1, 0.f);
            H1[j * 96 + tx + 64] = fmaxf(acc[r][2] + b2, 0.f);
        }
    }
    __syncthreads();

    for (int idx = tid; idx < 9216; idx += 256) WS[idx] = gw2[idx];
    __syncthreads();

    {
        float acc[12][3];
        #pragma unroll
        for (int r = 0; r < 12; r++) { acc[r][0] = 0.f; acc[r][1] = 0.f; acc[r][2] = 0.f; }
        for (int k = 0; k < 96; k++) {
            float w0 = WS[k * 96 + tx];
            float w1 = WS[k * 96 + tx + 32];
            float w2 = WS[k * 96 + tx + 64];
            #pragma unroll
            for (int r = 0; r < 12; r++) {
                float g = H1[(ty + (r << 3)) * 96 + k];
                acc[r][0] = fmaf(g, w0, acc[r][0]);
                acc[r][1] = fmaf(g, w1, acc[r][1]);
                acc[r][2] = fmaf(g, w2, acc[r][2]);
            }
        }
        float b0 = gb2[tx], b1 = gb2[tx + 32], b2 = gb2[tx + 64];
        #pragma unroll
        for (int r = 0; r < 12; r++) {
            int j = ty + (r << 3);
            GIN[j * 96 + tx]      = acc[r][0] + b0 + XS[j * 96 + tx];
            GIN[j * 96 + tx + 32] = acc[r][1] + b1 + XS[j * 96 + tx + 32];
            GIN[j * 96 + tx + 64] = acc[r][2] + b2 + XS[j * 96 + tx + 64];
        }
    }
    __syncthreads();

    if (tid < 96) {
        const int c = tid;
        float m = 0.f;
        for (int j = 0; j < 96; j++) m += GIN[j * 96 + c];
        m *= (1.f / 96.f);
        float v = 0.f;
        for (int j = 0; j < 96; j++) { float d = GIN[j * 96 + c] - m; v = fmaf(d, d, v); }
        v *= (1.f / 96.f);
        RED[c] = m;
        RED[96 + c] = rsqrtf(v + 1e-5f) * bnw[c];
    }
    __syncthreads();

    for (int idx = tid; idx < 9216; idx += 256) {
        int j = idx / 96, c = idx % 96;
        float out = (GIN[idx] - RED[c]) * RED[96 + c] + bnb[c];
        g_z[(size_t)j * (TT * DF) + t * DF + c] = out;
    }
}

// =====================================================================
// K2: zxbcdt = z (15360x96) @ in_proj (96x1158)
// 128x128 tile, 8x8 microtile, packed fp32x2 FFMA2 mainloop.
// =====================================================================
#define K2_SMEM_FLOATS (96*132 + 96*128)

__global__ void __launch_bounds__(256, 2) k2_inproj(const float* __restrict__ W) {
    extern __shared__ float sm[];
    float* As = sm;              // As[k*132 + m]
    float* Bs = As + 96 * 132;   // Bs[k*128 + n]

    const int m0 = blockIdx.x * 128;
    const int n0 = blockIdx.y * 128;
    const int tid = threadIdx.x;

    for (int idx = tid; idx < 128 * 24; idx += 256) {
        int m = idx / 24, k4 = idx % 24;
        float4 v = *reinterpret_cast<const float4*>(&g_z[(size_t)(m0 + m) * 96 + k4 * 4]);
        As[(k4 * 4 + 0) * 132 + m] = v.x;
        As[(k4 * 4 + 1) * 132 + m] = v.y;
        As[(k4 * 4 + 2) * 132 + m] = v.z;
        As[(k4 * 4 + 3) * 132 + m] = v.w;
    }
    for (int idx = tid; idx < 96 * 128; idx += 256) {
        int k = idx / 128, n = idx % 128;
        int gn = n0 + n;
        Bs[k * 128 + n] = (gn < DIN) ? W[(size_t)k * DIN + gn] : 0.f;
    }
    __syncthreads();

    const int tx = tid & 15;
    const int ty = tid >> 4;
    const int mt = ty * 8, nt = tx * 8;

    unsigned long long acc2[8][4];
    #pragma unroll
    for (int i = 0; i < 8; i++)
        #pragma unroll
        for (int j = 0; j < 4; j++) acc2[i][j] = 0ull;

    #pragma unroll 2
    for (int k = 0; k < 96; k++) {
        float4 a0 = *reinterpret_cast<const float4*>(&As[k * 132 + mt]);
        float4 a1 = *reinterpret_cast<const float4*>(&As[k * 132 + mt + 4]);
        float4 b0 = *reinterpret_cast<const float4*>(&Bs[k * 128 + nt]);
        float4 b1 = *reinterpret_cast<const float4*>(&Bs[k * 128 + nt + 4]);
        unsigned long long bp0 = pack2(b0.x, b0.y);
        unsigned long long bp1 = pack2(b0.z, b0.w);
        unsigned long long bp2 = pack2(b1.x, b1.y);
        unsigned long long bp3 = pack2(b1.z, b1.w);
        float av[8] = {a0.x, a0.y, a0.z, a0.w, a1.x, a1.y, a1.z, a1.w};
        #pragma unroll
        for (int i = 0; i < 8; i++) {
            unsigned long long ap = pack2(av[i], av[i]);
            ffma2(acc2[i][0], ap, bp0);
            ffma2(acc2[i][1], ap, bp1);
            ffma2(acc2[i][2], ap, bp2);
            ffma2(acc2[i][3], ap, bp3);
        }
    }

    #pragma unroll
    for (int i = 0; i < 8; i++) {
        size_t mrow = (size_t)(m0 + mt + i) * DINP;
        #pragma unroll
        for (int j = 0; j < 4; j++) {
            float lo, hi;
            unpack2(acc2[i][j], lo, hi);
            int n = n0 + nt + j * 2;
            if (n < DIN)     g_zx[mrow + n]     = lo;
            if (n + 1 < DIN) g_zx[mrow + n + 1] = hi;
        }
    }
}

// =====================================================================
// K3: depthwise causal conv(4) + SiLU on xBC = zx[:, 192:1152]
// =====================================================================
__global__ void k3_conv(const float* __restrict__ conv_w,
                        const float* __restrict__ conv_b) {
    int idx = blockIdx.x * 256 + threadIdx.x;
    if (idx >= MROWS * (CONVD / 4)) return;
    int c4 = idx % (CONVD / 4);
    int bl = idx / (CONVD / 4);
    int l  = bl % TT;
    int b  = bl / TT;
    const int c = c4 * 4;

    float4 acc = *reinterpret_cast<const float4*>(conv_b + c);
    float4 w0 = *reinterpret_cast<const float4*>(conv_w + (c + 0) * 4);
    float4 w1 = *reinterpret_cast<const float4*>(conv_w + (c + 1) * 4);
    float4 w2 = *reinterpret_cast<const float4*>(conv_w + (c + 2) * 4);
    float4 w3 = *reinterpret_cast<const float4*>(conv_w + (c + 3) * 4);
    const float wk[4][4] = {{w0.x, w1.x, w2.x, w3.x},
                            {w0.y, w1.y, w2.y, w3.y},
                            {w0.z, w1.z, w2.z, w3.z},
                            {w0.w, w1.w, w2.w, w3.w}};
    #pragma unroll
    for (int k = 0; k < 4; k++) {
        int li = l + k - 3;
        if (li >= 0) {
            float4 v = *reinterpret_cast<const float4*>(
                &g_zx[(size_t)(b * TT + li) * DINP + DINNER + c]);
            acc.x = fmaf(v.x, wk[k][0], acc.x);
            acc.y = fmaf(v.y, wk[k][1], acc.y);
            acc.z = fmaf(v.z, wk[k][2], acc.z);
            acc.w = fmaf(v.w, wk[k][3], acc.w);
        }
    }
    float4 o;
    o.x = siluf(acc.x); o.y = siluf(acc.y); o.z = siluf(acc.z); o.w = siluf(acc.w);
    *reinterpret_cast<float4*>(&g_xc[(size_t)bl * CONVD + c]) = o;
}

// =====================================================================
// K3b: precompute dt & dA per (b,h,l) — removes MUFU from scan loop
// =====================================================================
__global__ void k3b_dt(const float* __restrict__ A_log,
                       const float* __restrict__ dt_bias) {
    int idx = blockIdx.x * 256 + threadIdx.x;
    if (idx >= NB * NH * TT) return;
    int l = idx % TT;
    int bh = idx / TT;
    int h = bh % NH;
    int b = bh / NH;
    float dtr = g_zx[((size_t)b * TT + l) * DINP + (DIN - NH) + h];
    float dt = softplusf(dtr + dt_bias[h]);
    g_dt[idx] = dt;
    g_dA[idx] = expf(dt * (-expf(A_log[h])));
}

// =====================================================================
// K4: selective scan. block=(b,h); 256 threads hold state[32][64].
// Chunked smem staging (double-buffered), precomputed dt/dA.
// smem chunk layout per step s: [x:0..31 | B:32..95 | C:96..159]
// =====================================================================
__global__ void __launch_bounds__(256, 4) k4_scan(const float* __restrict__ Dpar) {
    const int b = blockIdx.x;
    const int h = blockIdx.y;
    const int tid = threadIdx.x;
    const int p = tid >> 3;
    const int kk = tid & 7;

    __shared__ float sdt[TT];
    __shared__ float sdA[TT];
    __shared__ float buf[2][CHUNK * 160];

    const float Dp = Dpar[h];

    {
        const float* dsrc = g_dt + (size_t)(b * NH + h) * TT;
        const float* asrc = g_dA + (size_t)(b * NH + h) * TT;
        for (int l = tid; l < TT; l += 256) {
            sdt[l] = dsrc[l];
            sdA[l] = asrc[l];
        }
    }

    const float* xbase = g_xc + (size_t)b * TT * CONVD;
    const int xoff = h * HD;
    const int boff = DINNER + h * DSTATE;
    const int coff = DINNER + NGROUPS * DSTATE + h * DSTATE;

    // chunk loader: 40 float4 per step (x:8, B:16, C:16)
    auto load_chunk = [&](int ci, float* dst) {
        for (int q = tid; q < CHUNK * 40; q += 256) {
            int s = q / 40, r = q % 40;
            const float* row = xbase + (size_t)(ci * CHUNK + s) * CONVD;
            int goff, doff;
            if (r < 8)       { goff = xoff + r * 4;         doff = r * 4; }
            else if (r < 24) { goff = boff + (r - 8) * 4;   doff = 32 + (r - 8) * 4; }
            else             { goff = coff + (r - 24) * 4;  doff = 96 + (r - 24) * 4; }
            *reinterpret_cast<float4*>(dst + s * 160 + doff) =
                *reinterpret_cast<const float4*>(row + goff);
        }
    };

    load_chunk(0, buf[0]);
    __syncthreads();

    float st[8];
    #pragma unroll
    for (int i = 0; i < 8; i++) st[i] = 0.f;

    float* yout = g_y + (size_t)b * TT * DINNER + h * HD + p;

    const int NCH = TT / CHUNK;
    for (int ci = 0; ci < NCH; ci++) {
        float* cur = buf[ci & 1];
        if (ci + 1 < NCH) load_chunk(ci + 1, buf[(ci + 1) & 1]);

        #pragma unroll
        for (int s = 0; s < CHUNK; s++) {
            const float* sp = cur + s * 160;
            const int l = ci * CHUNK + s;
            float dA = sdA[l];
            float dt = sdt[l];
            float x  = sp[p];
            float4 B0 = *reinterpret_cast<const float4*>(sp + 32 + kk * 8);
            float4 B1 = *reinterpret_cast<const float4*>(sp + 36 + kk * 8);
            float4 C0 = *reinterpret_cast<const float4*>(sp + 96 + kk * 8);
            float4 C1 = *reinterpret_cast<const float4*>(sp + 100 + kk * 8);

            float cf = dt * x;

            st[0] = fmaf(st[0], dA, cf * B0.x);
            st[1] = fmaf(st[1], dA, cf * B0.y);
            st[2] = fmaf(st[2], dA, cf * B0.z);
            st[3] = fmaf(st[3], dA, cf * B0.w);
            st[4] = fmaf(st[4], dA, cf * B1.x);
            st[5] = fmaf(st[5], dA, cf * B1.y);
            st[6] = fmaf(st[6], dA, cf * B1.z);
            st[7] = fmaf(st[7], dA, cf * B1.w);

            float yp = st[0] * C0.x + st[1] * C0.y + st[2] * C0.z + st[3] * C0.w
                     + st[4] * C1.x + st[5] * C1.y + st[6] * C1.z + st[7] * C1.w;
            yp += __shfl_down_sync(0xffffffffu, yp, 4);
            yp += __shfl_down_sync(0xffffffffu, yp, 2);
            yp += __shfl_down_sync(0xffffffffu, yp, 1);
            if (kk == 0) yout[(size_t)l * DINNER] = fmaf(Dp, x, yp);
        }
        __syncthreads();
    }
}

// =====================================================================
// K5: yg = y * silu(zg); RMSNorm over 192; partial sum over L chunk.
// =====================================================================
__global__ void k5_gate(const float* __restrict__ norm_w) {
    const int b = blockIdx.x;
    const int ch = blockIdx.y;
    const int c = threadIdx.x;  // 0..191
    const int warp = c >> 5, lane = c & 31;

    __shared__ float red[6];
    __shared__ float ssb;

    const float nw = norm_w[c];
    float acc = 0.f;

    for (int l = ch * 20; l < ch * 20 + 20; l++) {
        size_t r = (size_t)(b * TT + l);
        float y  = g_y[r * DINNER + c];
        float zv = g_zx[r * DINP + c];
        float yg = y * siluf(zv);
        float s = yg * yg;
        #pragma unroll
        for (int o = 16; o > 0; o >>= 1) s += __shfl_down_sync(0xffffffffu, s, o);
        if (lane == 0) red[warp] = s;
        __syncthreads();
        if (c == 0) {
            float tot = red[0] + red[1] + red[2] + red[3] + red[4] + red[5];
            ssb = rsqrtf(tot * (1.f / 192.f) + 1e-5f);
        }
        __syncthreads();
        acc = fmaf(yg * ssb, nw, acc);
    }
    g_sp[((size_t)b * 8 + ch) * DINNER + c] = acc;
}

// =====================================================================
// K6: e = (sum over L)/160 @ out_proj, then head.
// out layout: x1[96*96] | mu[96*64] | sigma[96*64]
// =====================================================================
__global__ void k6_head(const float* __restrict__ out_proj,
                        const float* __restrict__ ofw,
                        const float* __restrict__ ofb,
                        const float* __restrict__ mu_w,
                        const float* __restrict__ mu_b,
                        const float* __restrict__ sg_w,
                        const float* __restrict__ sg_b,
                        float* __restrict__ out) {
    const int b = blockIdx.x;
    const int tid = threadIdx.x;  // 0..95
    __shared__ float sb[192], es[96], x1s[96];

    for (int idx = tid; idx < 192; idx += 96) {
        float s = 0.f;
        #pragma unroll
        for (int chk = 0; chk < 8; chk++)
            s += g_sp[((size_t)b * 8 + chk) * DINNER + idx];
        sb[idx] = s * (1.f / 160.f);
    }
    __syncthreads();

    {
        float e = 0.f;
        for (int k = 0; k < 192; k++) e = fmaf(sb[k], out_proj[k * 96 + tid], e);
        es[tid] = e;
    }
    __syncthreads();

    {
        float v = ofb[tid];
        for (int k = 0; k < 96; k++) v = fmaf(es[k], ofw[k * 96 + tid], v);
        v = tanhf(v);
        v = eluf(v);
        x1s[tid] = v;
        out[(size_t)b * 96 + tid] = v;
    }
    __syncthreads();

    if (tid < 64) {
        float m = mu_b[tid], sg = sg_b[tid];
        for (int k = 0; k < 96; k++) {
            m  = fmaf(x1s[k], mu_w[k * 64 + tid], m);
            sg = fmaf(x1s[k], sg_w[k * 64 + tid], sg);
        }
        out[96 * 96 + (size_t)b * 64 + tid] = m;
        out[96 * 96 + 96 * 64 + (size_t)b * 64 + tid] = eluf(sg) + 1.f + 1e-14f;
    }
}

// =====================================================================
extern "C" void kernel_launch(void* const* d_in, const int* in_sizes, int n_in,
                              void* d_out, int out_size) {
    const float* input   = (const float*)d_in[0];
    const int*   hem     = (const int*)  d_in[1];
    const int*   subnet  = (const int*)  d_in[2];
    const float* gine_w1 = (const float*)d_in[3];
    const float* gine_b1 = (const float*)d_in[4];
    const float* gine_w2 = (const float*)d_in[5];
    const float* gine_b2 = (const float*)d_in[6];
    const float* bn_w    = (const float*)d_in[7];
    const float* bn_b    = (const float*)d_in[8];
    const float* hem_emb = (const float*)d_in[9];
    const float* sub_emb = (const float*)d_in[10];
    const float* in_proj = (const float*)d_in[11];
    const float* conv_w  = (const float*)d_in[12];
    const float* conv_b  = (const float*)d_in[13];
    const float* dt_bias = (const float*)d_in[14];
    const float* A_log   = (const float*)d_in[15];
    const float* Dparam  = (const float*)d_in[16];
    const float* norm_w  = (const float*)d_in[17];
    const float* out_proj= (const float*)d_in[18];
    const float* out_fc_w= (const float*)d_in[19];
    const float* out_fc_b= (const float*)d_in[20];
    const float* mu_w    = (const float*)d_in[21];
    const float* mu_b    = (const float*)d_in[22];
    const float* sigma_w = (const float*)d_in[23];
    const float* sigma_b = (const float*)d_in[24];

    const int smem1 = K1_SMEM_FLOATS * 4;
    const int smem2 = K2_SMEM_FLOATS * 4;
    cudaFuncSetAttribute(k1_embed_gnn, cudaFuncAttributeMaxDynamicSharedMemorySize, smem1);
    cudaFuncSetAttribute(k2_inproj,    cudaFuncAttributeMaxDynamicSharedMemorySize, smem2);

    k1_embed_gnn<<<TT, 256, smem1>>>(input, hem, subnet, gine_w1, gine_b1,
                                     gine_w2, gine_b2, bn_w, bn_b, hem_emb, sub_emb);
    k2_inproj<<<dim3(MROWS / 128, (DIN + 127) / 128), 256, smem2>>>(in_proj);
    k3_conv<<<(MROWS * (CONVD / 4) + 255) / 256, 256>>>(conv_w, conv_b);
    k3b_dt<<<(NB * NH * TT + 255) / 256, 256>>>(A_log, dt_bias);
    k4_scan<<<dim3(NB, NH), 256>>>(Dparam);
    k5_gate<<<dim3(NB, 8), 192>>>(norm_w);
    k6_head<<<NB, 96>>>(out_proj, out_fc_w, out_fc_b, mu_w, mu_b,
                        sigma_w, sigma_b, (float*)d_out);
}

// round 6
// speedup vs baseline: 1.1561x; 1.1249x over previous
#include <cuda_runtime.h>
#include <cuda_bf16.h>
#include <cstdint>

// ---------------- problem constants ----------------
#define NB 96       // nodes / mamba batch
#define TT 160      // sequence length
#define DF 96       // feature dim D
#define EMB 24
#define H2 48       // 2*EMB
#define DINNER 192
#define NGROUPS 6
#define DSTATE 64
#define NH 6        // heads
#define HD 32       // headdim
#define DIN 1158    // D_IN_PROJ (logical)
#define DINP 1160   // padded row stride for g_zx (16B-aligned rows)
#define CONVD 960   // CONV_DIM
#define MROWS (NB*TT)   // 15360
#define CHUNK 16    // k4 smem staging depth

// ---------------- scratch (static device allocations) ----------------
__device__ float g_z[(size_t)MROWS * DF];
__device__ float g_zx[(size_t)MROWS * DINP];
__device__ float g_xc[(size_t)MROWS * CONVD];
__device__ float g_y[(size_t)MROWS * DINNER];
__device__ float g_sp[(size_t)NB * 8 * DINNER];
__device__ float g_dt[(size_t)NB * NH * TT];
__device__ float g_dA[(size_t)NB * NH * TT];

__device__ __forceinline__ float softplusf(float x) {
    return fmaxf(x, 0.f) + log1pf(expf(-fabsf(x)));
}
__device__ __forceinline__ float siluf(float x) {
    return x / (1.f + expf(-x));
}
__device__ __forceinline__ float eluf(float x) {
    return x > 0.f ? x : expm1f(x);
}

__device__ __forceinline__ unsigned tf32_of(float x) {
    unsigned r;
    asm("cvt.rna.tf32.f32 %0, %1;" : "=r"(r) : "f"(x));
    return r;
}
__device__ __forceinline__ void mma_tf32(float* d, const unsigned* a, const unsigned* b) {
    asm("mma.sync.aligned.m16n8k8.row.col.f32.tf32.tf32.f32 "
        "{%0,%1,%2,%3},{%4,%5,%6,%7},{%8,%9},{%0,%1,%2,%3};"
        : "+f"(d[0]), "+f"(d[1]), "+f"(d[2]), "+f"(d[3])
        : "r"(a[0]), "r"(a[1]), "r"(a[2]), "r"(a[3]), "r"(b[0]), "r"(b[1]));
}

// =====================================================================
// K1: per-timestep block. embed-aggregate + 2x GEMM(96x96x96) + residual
//     + node-BatchNorm, writes z in (b, l, c) layout.
// =====================================================================
#define K1_SMEM_FLOATS (9216*4 + 4608 + 48 + 192)

__global__ void k1_embed_gnn(const float* __restrict__ input,
                             const int* __restrict__ hem,
                             const int* __restrict__ subnet,
                             const float* __restrict__ gw1,
                             const float* __restrict__ gb1,
                             const float* __restrict__ gw2,
                             const float* __restrict__ gb2,
                             const float* __restrict__ bnw,
                             const float* __restrict__ bnb,
                             const float* __restrict__ hem_emb,
                             const float* __restrict__ sub_emb) {
    extern __shared__ float sm[];
    float* XS  = sm;
    float* GIN = XS + 9216;
    float* H1  = GIN + 9216;
    float* WS  = H1 + 9216;
    float* ASM = WS + 9216;
    float* S1  = ASM + 4608;
    float* RED = S1 + 48;

    const int t = blockIdx.x;
    const int tid = threadIdx.x;

    for (int idx = tid; idx < 9216; idx += 256) {
        int i = idx / 96, c = idx % 96;
        XS[idx] = input[(size_t)i * (TT * DF) + t * DF + c];
    }
    for (int idx = tid; idx < 4608; idx += 256) {
        int j = idx / H2, c = idx % H2;
        ASM[idx] = (c < EMB) ? hem_emb[hem[j] * EMB + c]
                             : sub_emb[subnet[j] * EMB + (c - EMB)];
    }
    __syncthreads();

    if (tid < H2) {
        float s = 0.f;
        for (int i = 0; i < NB; i++)
            s += fmaxf(XS[i * 96 + tid] + ASM[i * H2 + tid], 0.f);
        S1[tid] = s;
    }
    __syncthreads();

    for (int idx = tid; idx < 9216; idx += 256) {
        int j = idx / 96, c = idx % 96;
        float g;
        if (c < H2) {
            g = XS[idx] + S1[c];
        } else {
            float a = ASM[j * H2 + (c - H2)];
            float s = 0.f;
            #pragma unroll 4
            for (int i = 0; i < NB; i++)
                s += fmaxf(XS[i * 96 + c] + a, 0.f);
            g = XS[idx] + s;
        }
        GIN[idx] = g;
    }
    __syncthreads();

    for (int idx = tid; idx < 9216; idx += 256) WS[idx] = gw1[idx];
    __syncthreads();

    const int tx = tid & 31;
    const int ty = tid >> 5;

    {
        float acc[12][3];
        #pragma unroll
        for (int r = 0; r < 12; r++) { acc[r][0] = 0.f; acc[r][1] = 0.f; acc[r][2] = 0.f; }
        for (int k = 0; k < 96; k++) {
            float w0 = WS[k * 96 + tx];
            float w1 = WS[k * 96 + tx + 32];
            float w2 = WS[k * 96 + tx + 64];
            #pragma unroll
            for (int r = 0; r < 12; r++) {
                float g = GIN[(ty + (r << 3)) * 96 + k];
                acc[r][0] = fmaf(g, w0, acc[r][0]);
                acc[r][1] = fmaf(g, w1, acc[r][1]);
                acc[r][2] = fmaf(g, w2, acc[r][2]);
            }
        }
        float b0 = gb1[tx], b1 = gb1[tx + 32], b2 = gb1[tx + 64];
        #pragma unroll
        for (int r = 0; r < 12; r++) {
            int j = ty + (r << 3);
            H1[j * 96 + tx]      = fmaxf(acc[r][0] + b0, 0.f);
            H1[j * 96 + tx + 32] = fmaxf(acc[r][1] + b1, 0.f);
            H1[j * 96 + tx + 64] = fmaxf(acc[r][2] + b2, 0.f);
        }
    }
    __syncthreads();

    for (int idx = tid; idx < 9216; idx += 256) WS[idx] = gw2[idx];
    __syncthreads();

    {
        float acc[12][3];
        #pragma unroll
        for (int r = 0; r < 12; r++) { acc[r][0] = 0.f; acc[r][1] = 0.f; acc[r][2] = 0.f; }
        for (int k = 0; k < 96; k++) {
            float w0 = WS[k * 96 + tx];
            float w1 = WS[k * 96 + tx + 32];
            float w2 = WS[k * 96 + tx + 64];
            #pragma unroll
            for (int r = 0; r < 12; r++) {
                float g = H1[(ty + (r << 3)) * 96 + k];
                acc[r][0] = fmaf(g, w0, acc[r][0]);
                acc[r][1] = fmaf(g, w1, acc[r][1]);
                acc[r][2] = fmaf(g, w2, acc[r][2]);
            }
        }
        float b0 = gb2[tx], b1 = gb2[tx + 32], b2 = gb2[tx + 64];
        #pragma unroll
        for (int r = 0; r < 12; r++) {
            int j = ty + (r << 3);
            GIN[j * 96 + tx]      = acc[r][0] + b0 + XS[j * 96 + tx];
            GIN[j * 96 + tx + 32] = acc[r][1] + b1 + XS[j * 96 + tx + 32];
            GIN[j * 96 + tx + 64] = acc[r][2] + b2 + XS[j * 96 + tx + 64];
        }
    }
    __syncthreads();

    if (tid < 96) {
        const int c = tid;
        float m = 0.f;
        for (int j = 0; j < 96; j++) m += GIN[j * 96 + c];
        m *= (1.f / 96.f);
        float v = 0.f;
        for (int j = 0; j < 96; j++) { float d = GIN[j * 96 + c] - m; v = fmaf(d, d, v); }
        v *= (1.f / 96.f);
        RED[c] = m;
        RED[96 + c] = rsqrtf(v + 1e-5f) * bnw[c];
    }
    __syncthreads();

    for (int idx = tid; idx < 9216; idx += 256) {
        int j = idx / 96, c = idx % 96;
        float out = (GIN[idx] - RED[c]) * RED[96 + c] + bnb[c];
        g_z[(size_t)j * (TT * DF) + t * DF + c] = out;
    }
}

// =====================================================================
// K2: zxbcdt = z (15360x96) @ in_proj (96x1158), tf32 tensor cores.
// Block tile 128x128, 8 warps of 32x64, mma.sync m16n8k8.
// smem holds tf32 bit patterns; stride 132 to avoid bank conflicts.
// =====================================================================
#define K2_SMEM_BYTES (96*132*2*4)

__global__ void __launch_bounds__(256, 2) k2_inproj(const float* __restrict__ W) {
    extern __shared__ unsigned smu[];
    unsigned* As = smu;              // [k*132 + m]
    unsigned* Bs = smu + 96 * 132;   // [k*132 + n]

    const int m0 = blockIdx.x * 128;
    const int n0 = blockIdx.y * 128;
    const int tid = threadIdx.x;

    // stage A (transposed to [k][m]) as tf32 bits
    for (int idx = tid; idx < 128 * 24; idx += 256) {
        int m = idx / 24, k4 = idx % 24;
        float4 v = *reinterpret_cast<const float4*>(&g_z[(size_t)(m0 + m) * 96 + k4 * 4]);
        As[(k4 * 4 + 0) * 132 + m] = tf32_of(v.x);
        As[(k4 * 4 + 1) * 132 + m] = tf32_of(v.y);
        As[(k4 * 4 + 2) * 132 + m] = tf32_of(v.z);
        As[(k4 * 4 + 3) * 132 + m] = tf32_of(v.w);
    }
    // stage B [k][n] as tf32 bits, zero-padded beyond DIN
    for (int idx = tid; idx < 96 * 128; idx += 256) {
        int k = idx / 128, n = idx % 128;
        int gn = n0 + n;
        float v = (gn < DIN) ? W[(size_t)k * DIN + gn] : 0.f;
        Bs[k * 132 + n] = tf32_of(v);
    }
    __syncthreads();

    const int lane = tid & 31;
    const int warp = tid >> 5;
    const int wm = warp & 3;      // 0..3 -> m offset wm*32
    const int wn = warp >> 2;     // 0..1 -> n offset wn*64
    const int gid = lane >> 2;    // 0..7
    const int tig = lane & 3;     // 0..3

    float acc[2][8][4];
    #pragma unroll
    for (int mi = 0; mi < 2; mi++)
        #pragma unroll
        for (int ni = 0; ni < 8; ni++)
            #pragma unroll
            for (int r = 0; r < 4; r++) acc[mi][ni][r] = 0.f;

    #pragma unroll
    for (int ks = 0; ks < 12; ks++) {
        const int k0 = ks * 8;
        unsigned a[2][4];
        #pragma unroll
        for (int mi = 0; mi < 2; mi++) {
            int mb = wm * 32 + mi * 16 + gid;
            a[mi][0] = As[(k0 + tig) * 132 + mb];
            a[mi][1] = As[(k0 + tig) * 132 + mb + 8];
            a[mi][2] = As[(k0 + tig + 4) * 132 + mb];
            a[mi][3] = As[(k0 + tig + 4) * 132 + mb + 8];
        }
        unsigned bf[8][2];
        #pragma unroll
        for (int ni = 0; ni < 8; ni++) {
            int nb = wn * 64 + ni * 8 + gid;
            bf[ni][0] = Bs[(k0 + tig) * 132 + nb];
            bf[ni][1] = Bs[(k0 + tig + 4) * 132 + nb];
        }
        #pragma unroll
        for (int mi = 0; mi < 2; mi++)
            #pragma unroll
            for (int ni = 0; ni < 8; ni++)
                mma_tf32(acc[mi][ni], a[mi], bf[ni]);
    }

    // store: rows gid & gid+8 of each 16-row tile; cols tig*2, tig*2+1
    #pragma unroll
    for (int mi = 0; mi < 2; mi++) {
        int r0 = m0 + wm * 32 + mi * 16 + gid;
        #pragma unroll
        for (int ni = 0; ni < 8; ni++) {
            int col = n0 + wn * 64 + ni * 8 + tig * 2;
            if (col + 1 < DINP) {
                float2 v0 = make_float2(acc[mi][ni][0], acc[mi][ni][1]);
                float2 v1 = make_float2(acc[mi][ni][2], acc[mi][ni][3]);
                *reinterpret_cast<float2*>(&g_zx[(size_t)r0 * DINP + col]) = v0;
                *reinterpret_cast<float2*>(&g_zx[(size_t)(r0 + 8) * DINP + col]) = v1;
            }
        }
    }
}

// =====================================================================
// K3: depthwise causal conv(4) + SiLU on xBC = zx[:, 192:1152]
// =====================================================================
__global__ void k3_conv(const float* __restrict__ conv_w,
                        const float* __restrict__ conv_b) {
    int idx = blockIdx.x * 256 + threadIdx.x;
    if (idx >= MROWS * (CONVD / 4)) return;
    int c4 = idx % (CONVD / 4);
    int bl = idx / (CONVD / 4);
    int l  = bl % TT;
    int b  = bl / TT;
    const int c = c4 * 4;

    float4 acc = *reinterpret_cast<const float4*>(conv_b + c);
    float4 w0 = *reinterpret_cast<const float4*>(conv_w + (c + 0) * 4);
    float4 w1 = *reinterpret_cast<const float4*>(conv_w + (c + 1) * 4);
    float4 w2 = *reinterpret_cast<const float4*>(conv_w + (c + 2) * 4);
    float4 w3 = *reinterpret_cast<const float4*>(conv_w + (c + 3) * 4);
    const float wk[4][4] = {{w0.x, w1.x, w2.x, w3.x},
                            {w0.y, w1.y, w2.y, w3.y},
                            {w0.z, w1.z, w2.z, w3.z},
                            {w0.w, w1.w, w2.w, w3.w}};
    #pragma unroll
    for (int k = 0; k < 4; k++) {
        int li = l + k - 3;
        if (li >= 0) {
            float4 v = *reinterpret_cast<const float4*>(
                &g_zx[(size_t)(b * TT + li) * DINP + DINNER + c]);
            acc.x = fmaf(v.x, wk[k][0], acc.x);
            acc.y = fmaf(v.y, wk[k][1], acc.y);
            acc.z = fmaf(v.z, wk[k][2], acc.z);
            acc.w = fmaf(v.w, wk[k][3], acc.w);
        }
    }
    float4 o;
    o.x = siluf(acc.x); o.y = siluf(acc.y); o.z = siluf(acc.z); o.w = siluf(acc.w);
    *reinterpret_cast<float4*>(&g_xc[(size_t)bl * CONVD + c]) = o;
}

// =====================================================================
// K3b: precompute dt & dA per (b,h,l) — removes MUFU from scan loop
// =====================================================================
__global__ void k3b_dt(const float* __restrict__ A_log,
                       const float* __restrict__ dt_bias) {
    int idx = blockIdx.x * 256 + threadIdx.x;
    if (idx >= NB * NH * TT) return;
    int l = idx % TT;
    int bh = idx / TT;
    int h = bh % NH;
    int b = bh / NH;
    float dtr = g_zx[((size_t)b * TT + l) * DINP + (DIN - NH) + h];
    float dt = softplusf(dtr + dt_bias[h]);
    g_dt[idx] = dt;
    g_dA[idx] = expf(dt * (-expf(A_log[h])));
}

// =====================================================================
// K4: selective scan. block=(b,h); 256 threads hold state[32][64].
// Chunked smem staging (double-buffered), precomputed dt/dA.
// =====================================================================
__global__ void __launch_bounds__(256, 4) k4_scan(const float* __restrict__ Dpar) {
    const int b = blockIdx.x;
    const int h = blockIdx.y;
    const int tid = threadIdx.x;
    const int p = tid >> 3;
    const int kk = tid & 7;

    __shared__ float sdt[TT];
    __shared__ float sdA[TT];
    __shared__ float buf[2][CHUNK * 160];

    const float Dp = Dpar[h];

    {
        const float* dsrc = g_dt + (size_t)(b * NH + h) * TT;
        const float* asrc = g_dA + (size_t)(b * NH + h) * TT;
        for (int l = tid; l < TT; l += 256) {
            sdt[l] = dsrc[l];
            sdA[l] = asrc[l];
        }
    }

    const float* xbase = g_xc + (size_t)b * TT * CONVD;
    const int xoff = h * HD;
    const int boff = DINNER + h * DSTATE;
    const int coff = DINNER + NGROUPS * DSTATE + h * DSTATE;

    auto load_chunk = [&](int ci, float* dst) {
        for (int q = tid; q < CHUNK * 40; q += 256) {
            int s = q / 40, r = q % 40;
            const float* row = xbase + (size_t)(ci * CHUNK + s) * CONVD;
            int goff, doff;
            if (r < 8)       { goff = xoff + r * 4;         doff = r * 4; }
            else if (r < 24) { goff = boff + (r - 8) * 4;   doff = 32 + (r - 8) * 4; }
            else             { goff = coff + (r - 24) * 4;  doff = 96 + (r - 24) * 4; }
            *reinterpret_cast<float4*>(dst + s * 160 + doff) =
                *reinterpret_cast<const float4*>(row + goff);
        }
    };

    load_chunk(0, buf[0]);
    __syncthreads();

    float st[8];
    #pragma unroll
    for (int i = 0; i < 8; i++) st[i] = 0.f;

    float* yout = g_y + (size_t)b * TT * DINNER + h * HD + p;

    const int NCH = TT / CHUNK;
    for (int ci = 0; ci < NCH; ci++) {
        float* cur = buf[ci & 1];
        if (ci + 1 < NCH) load_chunk(ci + 1, buf[(ci + 1) & 1]);

        #pragma unroll
        for (int s = 0; s < CHUNK; s++) {
            const float* sp = cur + s * 160;
            const int l = ci * CHUNK + s;
            float dA = sdA[l];
            float dt = sdt[l];
            float x  = sp[p];
            float4 B0 = *reinterpret_cast<const float4*>(sp + 32 + kk * 8);
            float4 B1 = *reinterpret_cast<const float4*>(sp + 36 + kk * 8);
            float4 C0 = *reinterpret_cast<const float4*>(sp + 96 + kk * 8);
            float4 C1 = *reinterpret_cast<const float4*>(sp + 100 + kk * 8);

            float cf = dt * x;

            st[0] = fmaf(st[0], dA, cf * B0.x);
            st[1] = fmaf(st[1], dA, cf * B0.y);
            st[2] = fmaf(st[2], dA, cf * B0.z);
            st[3] = fmaf(st[3], dA, cf * B0.w);
            st[4] = fmaf(st[4], dA, cf * B1.x);
            st[5] = fmaf(st[5], dA, cf * B1.y);
            st[6] = fmaf(st[6], dA, cf * B1.z);
            st[7] = fmaf(st[7], dA, cf * B1.w);

            float yp = st[0] * C0.x + st[1] * C0.y + st[2] * C0.z + st[3] * C0.w
                     + st[4] * C1.x + st[5] * C1.y + st[6] * C1.z + st[7] * C1.w;
            yp += __shfl_down_sync(0xffffffffu, yp, 4);
            yp += __shfl_down_sync(0xffffffffu, yp, 2);
            yp += __shfl_down_sync(0xffffffffu, yp, 1);
            if (kk == 0) yout[(size_t)l * DINNER] = fmaf(Dp, x, yp);
        }
        __syncthreads();
    }
}

// =====================================================================
// K5: yg = y * silu(zg); RMSNorm over 192; partial sum over L chunk.
// =====================================================================
__global__ void k5_gate(const float* __restrict__ norm_w) {
    const int b = blockIdx.x;
    const int ch = blockIdx.y;
    const int c = threadIdx.x;  // 0..191
    const int warp = c >> 5, lane = c & 31;

    __shared__ float red[6];
    __shared__ float ssb;

    const float nw = norm_w[c];
    float acc = 0.f;

    for (int l = ch * 20; l < ch * 20 + 20; l++) {
        size_t r = (size_t)(b * TT + l);
        float y  = g_y[r * DINNER + c];
        float zv = g_zx[r * DINP + c];
        float yg = y * siluf(zv);
        float s = yg * yg;
        #pragma unroll
        for (int o = 16; o > 0; o >>= 1) s += __shfl_down_sync(0xffffffffu, s, o);
        if (lane == 0) red[warp] = s;
        __syncthreads();
        if (c == 0) {
            float tot = red[0] + red[1] + red[2] + red[3] + red[4] + red[5];
            ssb = rsqrtf(tot * (1.f / 192.f) + 1e-5f);
        }
        __syncthreads();
        acc = fmaf(yg * ssb, nw, acc);
    }
    g_sp[((size_t)b * 8 + ch) * DINNER + c] = acc;
}

// =====================================================================
// K6: e = (sum over L)/160 @ out_proj, then head.
// out layout: x1[96*96] | mu[96*64] | sigma[96*64]
// =====================================================================
__global__ void k6_head(const float* __restrict__ out_proj,
                        const float* __restrict__ ofw,
                        const float* __restrict__ ofb,
                        const float* __restrict__ mu_w,
                        const float* __restrict__ mu_b,
                        const float* __restrict__ sg_w,
                        const float* __restrict__ sg_b,
                        float* __restrict__ out) {
    const int b = blockIdx.x;
    const int tid = threadIdx.x;  // 0..95
    __shared__ float sb[192], es[96], x1s[96];

    for (int idx = tid; idx < 192; idx += 96) {
        float s = 0.f;
        #pragma unroll
        for (int chk = 0; chk < 8; chk++)
            s += g_sp[((size_t)b * 8 + chk) * DINNER + idx];
        sb[idx] = s * (1.f / 160.f);
    }
    __syncthreads();

    {
        float e = 0.f;
        for (int k = 0; k < 192; k++) e = fmaf(sb[k], out_proj[k * 96 + tid], e);
        es[tid] = e;
    }
    __syncthreads();

    {
        float v = ofb[tid];
        for (int k = 0; k < 96; k++) v = fmaf(es[k], ofw[k * 96 + tid], v);
        v = tanhf(v);
        v = eluf(v);
        x1s[tid] = v;
        out[(size_t)b * 96 + tid] = v;
    }
    __syncthreads();

    if (tid < 64) {
        float m = mu_b[tid], sg = sg_b[tid];
        for (int k = 0; k < 96; k++) {
            m  = fmaf(x1s[k], mu_w[k * 64 + tid], m);
            sg = fmaf(x1s[k], sg_w[k * 64 + tid], sg);
        }
        out[96 * 96 + (size_t)b * 64 + tid] = m;
        out[96 * 96 + 96 * 64 + (size_t)b * 64 + tid] = eluf(sg) + 1.f + 1e-14f;
    }
}

// =====================================================================
extern "C" void kernel_launch(void* const* d_in, const int* in_sizes, int n_in,
                              void* d_out, int out_size) {
    const float* input   = (const float*)d_in[0];
    const int*   hem     = (const int*)  d_in[1];
    const int*   subnet  = (const int*)  d_in[2];
    const float* gine_w1 = (const float*)d_in[3];
    const float* gine_b1 = (const float*)d_in[4];
    const float* gine_w2 = (const float*)d_in[5];
    const float* gine_b2 = (const float*)d_in[6];
    const float* bn_w    = (const float*)d_in[7];
    const float* bn_b    = (const float*)d_in[8];
    const float* hem_emb = (const float*)d_in[9];
    const float* sub_emb = (const float*)d_in[10];
    const float* in_proj = (const float*)d_in[11];
    const float* conv_w  = (const float*)d_in[12];
    const float* conv_b  = (const float*)d_in[13];
    const float* dt_bias = (const float*)d_in[14];
    const float* A_log   = (const float*)d_in[15];
    const float* Dparam  = (const float*)d_in[16];
    const float* norm_w  = (const float*)d_in[17];
    const float* out_proj= (const float*)d_in[18];
    const float* out_fc_w= (const float*)d_in[19];
    const float* out_fc_b= (const float*)d_in[20];
    const float* mu_w    = (const float*)d_in[21];
    const float* mu_b    = (const float*)d_in[22];
    const float* sigma_w = (const float*)d_in[23];
    const float* sigma_b = (const float*)d_in[24];

    const int smem1 = K1_SMEM_FLOATS * 4;
    cudaFuncSetAttribute(k1_embed_gnn, cudaFuncAttributeMaxDynamicSharedMemorySize, smem1);
    cudaFuncSetAttribute(k2_inproj,    cudaFuncAttributeMaxDynamicSharedMemorySize, K2_SMEM_BYTES);

    k1_embed_gnn<<<TT, 256, smem1>>>(input, hem, subnet, gine_w1, gine_b1,
                                     gine_w2, gine_b2, bn_w, bn_b, hem_emb, sub_emb);
    k2_inproj<<<dim3(MROWS / 128, 10), 256, K2_SMEM_BYTES>>>(in_proj);
    k3_conv<<<(MROWS * (CONVD / 4) + 255) / 256, 256>>>(conv_w, conv_b);
    k3b_dt<<<(NB * NH * TT + 255) / 256, 256>>>(A_log, dt_bias);
    k4_scan<<<dim3(NB, NH), 256>>>(Dparam);
    k5_gate<<<dim3(NB, 8), 192>>>(norm_w);
    k6_head<<<NB, 96>>>(out_proj, out_fc_w, out_fc_b, mu_w, mu_b,
                        sigma_w, sigma_b, (float*)d_out);
}